// round 14
// baseline (speedup 1.0000x reference)
#include <cuda_runtime.h>
#include <math.h>

// CapsuleLayer dynamic routing v11 (resubmit after infra failure): BARRIER-FREE
// fused pass. One warp owns one (n-chunk, c) with ALL 64 batch rows: agreement
// reduce = 5x shfl_xor butterfly (no __syncthreads in main loop); every lane
// redundantly computes e = exp(b + a/64) and immediately accumulates s += e*t.

#define BB 64
#define NN 2304
#define CC 32
#define OO 16
#define II 8
#define CO 512
#define WROW 4096     // C*O*I floats per n
// pass0 tiling (proven k_sj)
#define NCHUNK 72
#define NPC 32
#define BG 16
#define BP 8
// fused tiling
#define NC2 144
#define NP2 16        // NN / NC2

__device__ float g_spart[(size_t)NC2 * BB * CO];  // 18.9 MB
__device__ float g_v[BB * CO];
__device__ float g_b[NN * CC];
__device__ float g_epart[NC2 * CC];
__device__ float g_inv[CC];

typedef unsigned long long u64;

__device__ __forceinline__ u64 pk2(float lo, float hi) {
    u64 r; asm("mov.b64 %0,{%1,%2};" : "=l"(r) : "f"(lo), "f"(hi)); return r;
}
__device__ __forceinline__ float2 unpk(u64 v) {
    float2 r; asm("mov.b64 {%0,%1},%2;" : "=f"(r.x), "=f"(r.y) : "l"(v)); return r;
}
__device__ __forceinline__ u64 ffma2(u64 a, u64 b, u64 c) {
    u64 d; asm("fma.rn.f32x2 %0,%1,%2,%3;" : "=l"(d) : "l"(a), "l"(b), "l"(c)); return d;
}
__device__ __forceinline__ u64 fmul2(u64 a, u64 b) {
    u64 d; asm("mul.rn.f32x2 %0,%1,%2;" : "=l"(d) : "l"(a), "l"(b)); return d;
}

// ---------------------------------------------------------------------------
// k_sj: pass0 s partials with uniform weight 1/N (proven v6 kernel).
// ---------------------------------------------------------------------------
__global__ __launch_bounds__(256, 2)
void k_sj(const float* __restrict__ x, const float* __restrict__ W)
{
    const int chunk = blockIdx.x;
    const int bg    = blockIdx.y;
    const int t     = threadIdx.x;
    const int n0    = chunk * NPC;

    __shared__ ulonglong2 xs[4][BP][NPC];   // 16KB

    const float4* x4 = (const float4*)x;
    {
        int bp = t >> 5;
        int nn = t & 31;
        const float4* xp0 = x4 + ((size_t)(bg * BG + 2 * bp) * NN + (n0 + nn)) * 2;
        const float4* xp1 = x4 + ((size_t)(bg * BG + 2 * bp + 1) * NN + (n0 + nn)) * 2;
        float4 a0 = xp0[0], a1 = xp0[1];
        float4 c0 = xp1[0], c1 = xp1[1];
        xs[0][bp][nn] = make_ulonglong2(pk2(a0.x, c0.x), pk2(a0.y, c0.y));
        xs[1][bp][nn] = make_ulonglong2(pk2(a0.z, c0.z), pk2(a0.w, c0.w));
        xs[2][bp][nn] = make_ulonglong2(pk2(a1.x, c1.x), pk2(a1.y, c1.y));
        xs[3][bp][nn] = make_ulonglong2(pk2(a1.z, c1.z), pk2(a1.w, c1.w));
    }
    __syncthreads();

    u64 acc0[BP], acc1[BP];
#pragma unroll
    for (int bp = 0; bp < BP; bp++) { acc0[bp] = 0ull; acc1[bp] = 0ull; }

    const float4* wp = (const float4*)(W + (size_t)n0 * WROW + (size_t)(2 * t) * II);
    float4 wa0 = wp[0], wa1 = wp[1], wb0 = wp[2], wb1 = wp[3];
    const float cw = 1.0f / (float)NN;

    for (int nn = 0; nn < NPC; nn++) {
        u64 wc0[8], wc1[8];
        {
            float m;
            m = wa0.x * cw; wc0[0] = pk2(m, m);
            m = wa0.y * cw; wc0[1] = pk2(m, m);
            m = wa0.z * cw; wc0[2] = pk2(m, m);
            m = wa0.w * cw; wc0[3] = pk2(m, m);
            m = wa1.x * cw; wc0[4] = pk2(m, m);
            m = wa1.y * cw; wc0[5] = pk2(m, m);
            m = wa1.z * cw; wc0[6] = pk2(m, m);
            m = wa1.w * cw; wc0[7] = pk2(m, m);
            m = wb0.x * cw; wc1[0] = pk2(m, m);
            m = wb0.y * cw; wc1[1] = pk2(m, m);
            m = wb0.z * cw; wc1[2] = pk2(m, m);
            m = wb0.w * cw; wc1[3] = pk2(m, m);
            m = wb1.x * cw; wc1[4] = pk2(m, m);
            m = wb1.y * cw; wc1[5] = pk2(m, m);
            m = wb1.z * cw; wc1[6] = pk2(m, m);
            m = wb1.w * cw; wc1[7] = pk2(m, m);
        }
        if (nn + 1 < NPC) {
            const float4* wn = wp + (size_t)(nn + 1) * (WROW / 4);
            wa0 = wn[0]; wa1 = wn[1]; wb0 = wn[2]; wb1 = wn[3];
        }
#pragma unroll
        for (int bp = 0; bp < BP; bp++) {
            ulonglong2 x01 = xs[0][bp][nn];
            ulonglong2 x23 = xs[1][bp][nn];
            ulonglong2 x45 = xs[2][bp][nn];
            ulonglong2 x67 = xs[3][bp][nn];
            u64 a0 = acc0[bp], a1 = acc1[bp];
            a0 = ffma2(wc0[0], x01.x, a0); a1 = ffma2(wc1[0], x01.x, a1);
            a0 = ffma2(wc0[1], x01.y, a0); a1 = ffma2(wc1[1], x01.y, a1);
            a0 = ffma2(wc0[2], x23.x, a0); a1 = ffma2(wc1[2], x23.x, a1);
            a0 = ffma2(wc0[3], x23.y, a0); a1 = ffma2(wc1[3], x23.y, a1);
            a0 = ffma2(wc0[4], x45.x, a0); a1 = ffma2(wc1[4], x45.x, a1);
            a0 = ffma2(wc0[5], x45.y, a0); a1 = ffma2(wc1[5], x45.y, a1);
            a0 = ffma2(wc0[6], x67.x, a0); a1 = ffma2(wc1[6], x67.x, a1);
            a0 = ffma2(wc0[7], x67.y, a0); a1 = ffma2(wc1[7], x67.y, a1);
            acc0[bp] = a0; acc1[bp] = a1;
        }
    }

    float* sp = g_spart + ((size_t)chunk * BB + (size_t)bg * BG) * CO + 2 * t;
#pragma unroll
    for (int bp = 0; bp < BP; bp++) {
        float2 f0 = unpk(acc0[bp]);
        float2 f1 = unpk(acc1[bp]);
        *(float2*)(sp + (size_t)(2 * bp) * CO)     = make_float2(f0.x, f1.x);
        *(float2*)(sp + (size_t)(2 * bp + 1) * CO) = make_float2(f0.y, f1.y);
    }
}

// ---------------------------------------------------------------------------
// k_fused2: barrier-free fused agreement + b-update + exp + weighted-s.
// block = (n-chunk of 16, c-group of 8 warps); warp owns one c, ALL 64 b.
// lane = bq(0..7: 8 b each as 4 b-pairs) x oq(0..3: 4 consecutive o).
// Per n: t (128 FFMA2) -> dot t.v -> 5x shfl_xor -> e=exp (all lanes) ->
// sacc += e*t. No __syncthreads in the loop.
// ---------------------------------------------------------------------------
__global__ __launch_bounds__(256, 1)
void k_fused2(const float* __restrict__ x, const float* __restrict__ W, int first)
{
    const int chunk = blockIdx.x;
    const int cg    = blockIdx.y;          // 0..3 (8 c per block)
    const int tid   = threadIdx.x;
    const int w     = tid >> 5;
    const int lane  = tid & 31;
    const int c     = cg * 8 + w;
    const int n0    = chunk * NP2;
    const int bq    = lane >> 2;           // 0..7
    const int oq    = lane & 3;            // 0..3
    const int co0   = c * OO + oq * 4;

    __shared__ ulonglong2 xs[4][32][NP2];   // 32KB: all 64 b, b-pair packed

    {
        const float4* x4 = (const float4*)x;
        for (int i = tid; i < 32 * NP2; i += 256) {
            int bpg = i >> 4;
            int nn  = i & 15;
            const float4* xp0 = x4 + ((size_t)(2 * bpg) * NN + (n0 + nn)) * 2;
            const float4* xp1 = x4 + ((size_t)(2 * bpg + 1) * NN + (n0 + nn)) * 2;
            float4 a0 = xp0[0], a1 = xp0[1];
            float4 c0 = xp1[0], c1 = xp1[1];
            xs[0][bpg][nn] = make_ulonglong2(pk2(a0.x, c0.x), pk2(a0.y, c0.y));
            xs[1][bpg][nn] = make_ulonglong2(pk2(a0.z, c0.z), pk2(a0.w, c0.w));
            xs[2][bpg][nn] = make_ulonglong2(pk2(a1.x, c1.x), pk2(a1.y, c1.y));
            xs[3][bpg][nn] = make_ulonglong2(pk2(a1.z, c1.z), pk2(a1.w, c1.w));
        }
    }

    // v: thread's 4 b-pairs x 4 consecutive o, b-pair packed
    u64 vv[4][4];
#pragma unroll
    for (int j = 0; j < 4; j++) {
        int be = (bq * 4 + j) * 2;
        float4 va = *(const float4*)(g_v + (size_t)be * CO + co0);
        float4 vb = *(const float4*)(g_v + (size_t)(be + 1) * CO + co0);
        vv[j][0] = pk2(va.x, vb.x);
        vv[j][1] = pk2(va.y, vb.y);
        vv[j][2] = pk2(va.z, vb.z);
        vv[j][3] = pk2(va.w, vb.w);
    }
    __syncthreads();   // xs ready (only barrier in the kernel)

    u64 sacc[4][4];
#pragma unroll
    for (int j = 0; j < 4; j++)
#pragma unroll
        for (int o = 0; o < 4; o++) sacc[j][o] = 0ull;
    float esum = 0.0f;

    // W: thread's slice = floats [c*128 + oq*32 .. +32) of each n row
    const float4* wbase = (const float4*)(W + (size_t)n0 * WROW + c * 128 + oq * 32);
    float4 wbuf[8];
#pragma unroll
    for (int k = 0; k < 8; k++) wbuf[k] = wbase[k];
    float bold = first ? 0.0f : g_b[(size_t)n0 * CC + c];

    for (int nn = 0; nn < NP2; nn++) {
        // build wd from wbuf (dup b-pair lanes), then prefetch next n
        u64 wd[4][8];
#pragma unroll
        for (int o = 0; o < 4; o++) {
            float4 A = wbuf[2 * o], B = wbuf[2 * o + 1];
            wd[o][0] = pk2(A.x, A.x); wd[o][1] = pk2(A.y, A.y);
            wd[o][2] = pk2(A.z, A.z); wd[o][3] = pk2(A.w, A.w);
            wd[o][4] = pk2(B.x, B.x); wd[o][5] = pk2(B.y, B.y);
            wd[o][6] = pk2(B.z, B.z); wd[o][7] = pk2(B.w, B.w);
        }
        float bnext = 0.0f;
        if (nn + 1 < NP2) {
            const float4* wn = wbase + (size_t)(nn + 1) * (WROW / 4);
#pragma unroll
            for (int k = 0; k < 8; k++) wbuf[k] = wn[k];
            if (!first) bnext = g_b[(size_t)(n0 + nn + 1) * CC + c];
        }

        u64 t4[4][4];
        u64 pacc = 0ull;
#pragma unroll
        for (int j = 0; j < 4; j++) {
            int bp = bq * 4 + j;
            ulonglong2 x01 = xs[0][bp][nn];
            ulonglong2 x23 = xs[1][bp][nn];
            ulonglong2 x45 = xs[2][bp][nn];
            ulonglong2 x67 = xs[3][bp][nn];
#pragma unroll
            for (int o = 0; o < 4; o++) {
                u64 a = fmul2(wd[o][0], x01.x);
                a = ffma2(wd[o][1], x01.y, a);
                a = ffma2(wd[o][2], x23.x, a);
                a = ffma2(wd[o][3], x23.y, a);
                a = ffma2(wd[o][4], x45.x, a);
                a = ffma2(wd[o][5], x45.y, a);
                a = ffma2(wd[o][6], x67.x, a);
                a = ffma2(wd[o][7], x67.y, a);
                t4[j][o] = a;
                pacc = ffma2(a, vv[j][o], pacc);
            }
        }

        // warp-wide butterfly: all lanes get full sum over (b, o)
        float2 pv = unpk(pacc);
        float p = pv.x + pv.y;
        p += __shfl_xor_sync(0xffffffffu, p, 16);
        p += __shfl_xor_sync(0xffffffffu, p, 8);
        p += __shfl_xor_sync(0xffffffffu, p, 4);
        p += __shfl_xor_sync(0xffffffffu, p, 2);
        p += __shfl_xor_sync(0xffffffffu, p, 1);

        float bnew = bold + p * (1.0f / (float)BB);
        float e = expf(bnew);
        if (first && lane == 0)
            g_b[(size_t)(n0 + nn) * CC + c] = bnew;
        esum += e;
        u64 ed = pk2(e, e);
#pragma unroll
        for (int j = 0; j < 4; j++)
#pragma unroll
            for (int o = 0; o < 4; o++)
                sacc[j][o] = ffma2(ed, t4[j][o], sacc[j][o]);
        bold = bnext;
    }

    // store s partials: per b-pair, 4 consecutive co -> 2 STG.128
    float* sp = g_spart + (size_t)chunk * BB * CO;
#pragma unroll
    for (int j = 0; j < 4; j++) {
        int be = (bq * 4 + j) * 2;
        float2 f0 = unpk(sacc[j][0]);
        float2 f1 = unpk(sacc[j][1]);
        float2 f2 = unpk(sacc[j][2]);
        float2 f3 = unpk(sacc[j][3]);
        *(float4*)(sp + (size_t)be * CO + co0)       = make_float4(f0.x, f1.x, f2.x, f3.x);
        *(float4*)(sp + (size_t)(be + 1) * CO + co0) = make_float4(f0.y, f1.y, f2.y, f3.y);
    }
    if (lane == 0)
        g_epart[chunk * CC + c] = esum;
}

// ---------------------------------------------------------------------------
// k_squash: float2 partial reduce over nch chunks + squash. 128 blocks x 128.
// ---------------------------------------------------------------------------
__global__ void k_squash(float* __restrict__ dout, int nch, int uniform, int final_pass)
{
    int id2 = blockIdx.x * 128 + threadIdx.x;   // 0..16383 (b*256 + co/2)
    const float2* sp = (const float2*)g_spart;
    float sx = 0.0f, sy = 0.0f;
#pragma unroll 4
    for (int ch = 0; ch < nch; ch++) {
        float2 p = sp[(size_t)ch * 16384 + id2];
        sx += p.x; sy += p.y;
    }
    int c = (id2 >> 3) & 31;
    float scale = uniform ? 1.0f : g_inv[c];
    sx *= scale; sy *= scale;
    float2 v;
    v.x = sx * fabsf(sx) / (1.0f + sx * sx);
    v.y = sy * fabsf(sy) / (1.0f + sy * sy);
    if (final_pass) ((float2*)dout)[id2] = v;
    else            ((float2*)g_v)[id2]  = v;
}

// ---------------------------------------------------------------------------
// k_esum: per-c total of e over chunk partials, store reciprocal.
// ---------------------------------------------------------------------------
__global__ void k_esum()
{
    const int c = blockIdx.x;
    const int t = threadIdx.x;
    __shared__ float red[256];
    float s = 0.0f;
    for (int i = t; i < NC2; i += 256)
        s += g_epart[i * CC + c];
    red[t] = s;
    __syncthreads();
    for (int off = 128; off > 0; off >>= 1) {
        if (t < off) red[t] += red[t + off];
        __syncthreads();
    }
    if (t == 0) g_inv[c] = 1.0f / red[0];
}

// ---------------------------------------------------------------------------
extern "C" void kernel_launch(void* const* d_in, const int* in_sizes, int n_in,
                              void* d_out, int out_size)
{
    const float* x = (const float*)d_in[0];   // [B, N, I]
    const float* W = (const float*)d_in[1];   // [N, C, O, I]
    float* out = (float*)d_out;               // [B, C, O, 1]

    dim3 g0(NCHUNK, 4);
    dim3 gf(NC2, 4);

    // iteration 0: uniform-weight s -> v0
    k_sj<<<g0, 256>>>(x, W);
    k_squash<<<128, 128>>>(out, NCHUNK, 1, 0);

    // fused: agreement(v0) -> b1, e1 -> s1 partials (barrier-free)
    k_fused2<<<gf, 256>>>(x, W, 1);
    k_esum<<<CC, 256>>>();
    k_squash<<<128, 128>>>(out, NC2, 0, 0);

    // fused: agreement(v1) -> b2, e2 -> s2 partials
    k_fused2<<<gf, 256>>>(x, W, 0);
    k_esum<<<CC, 256>>>();
    k_squash<<<128, 128>>>(out, NC2, 0, 1);
}

// round 15
// speedup vs baseline: 1.0583x; 1.0583x over previous
#include <cuda_runtime.h>
#include <math.h>

// CapsuleLayer dynamic routing v12: v6 structure (best, 219.2us) with the
// bcomb+esum pair merged into ONE coalesced route kernel via layout change:
// g_bupd stored [bg][c][n] and g_b stored [c][n] so the per-c route block
// reads contiguous rows (R6's k_route failed on strided loads, not on fusion).

#define BB 64
#define NN 2304
#define CC 32
#define OO 16
#define II 8
#define CO 512
#define WROW 4096     // C*O*I floats per n
#define NCHUNK 72
#define NPC 32        // NN / NCHUNK
#define BG 16         // batch rows per block
#define BP 8          // b-pairs per block
#define NBG 4

__device__ float g_spart[(size_t)NCHUNK * BB * CO];  // 9.4 MB
__device__ float g_v[BB * CO];
__device__ float g_bupd[NBG * CC * NN];   // [bg][c][n]  (coalesced for route)
__device__ float g_b[CC * NN];            // [c][n]
__device__ float g_e[NN * CC];            // [n][c]      (row-contig for k_sj)
__device__ float g_inv[CC];

typedef unsigned long long u64;

__device__ __forceinline__ u64 pk2(float lo, float hi) {
    u64 r; asm("mov.b64 %0,{%1,%2};" : "=l"(r) : "f"(lo), "f"(hi)); return r;
}
__device__ __forceinline__ float2 unpk(u64 v) {
    float2 r; asm("mov.b64 {%0,%1},%2;" : "=f"(r.x), "=f"(r.y) : "l"(v)); return r;
}
__device__ __forceinline__ u64 ffma2(u64 a, u64 b, u64 c) {
    u64 d; asm("fma.rn.f32x2 %0,%1,%2,%3;" : "=l"(d) : "l"(a), "l"(b), "l"(c)); return d;
}
__device__ __forceinline__ u64 fmul2(u64 a, u64 b) {
    u64 d; asm("mul.rn.f32x2 %0,%1,%2;" : "=l"(d) : "l"(a), "l"(b)); return d;
}

// shared x tile: xs[ipair(4)][bp(8)][nn(32)] of ulonglong2 = 16KB
#define XS_LOAD(xs, x4, bg, n0, t)                                              \
    {                                                                            \
        int bp = (t) >> 5;                                                       \
        int nn = (t) & 31;                                                       \
        const float4* xp0 = (x4) + ((size_t)((bg) * BG + 2 * bp) * NN + ((n0) + nn)) * 2; \
        const float4* xp1 = (x4) + ((size_t)((bg) * BG + 2 * bp + 1) * NN + ((n0) + nn)) * 2; \
        float4 a0 = xp0[0], a1 = xp0[1];                                         \
        float4 c0 = xp1[0], c1 = xp1[1];                                         \
        xs[0][bp][nn] = make_ulonglong2(pk2(a0.x, c0.x), pk2(a0.y, c0.y));       \
        xs[1][bp][nn] = make_ulonglong2(pk2(a0.z, c0.z), pk2(a0.w, c0.w));       \
        xs[2][bp][nn] = make_ulonglong2(pk2(a1.x, c1.x), pk2(a1.y, c1.y));       \
        xs[3][bp][nn] = make_ulonglong2(pk2(a1.z, c1.z), pk2(a1.w, c1.w));       \
    }

// ---------------------------------------------------------------------------
// k_sj: s partials. block = (n-chunk of 32, b-group of 16); 256 threads.
// Thread owns co pair (2t,2t+1); acc lanes are b-pairs; a0/a1 interleaved.
// ---------------------------------------------------------------------------
__global__ __launch_bounds__(256, 2)
void k_sj(const float* __restrict__ x, const float* __restrict__ W, int use_e)
{
    const int chunk = blockIdx.x;
    const int bg    = blockIdx.y;
    const int t     = threadIdx.x;
    const int n0    = chunk * NPC;
    const int c     = t >> 3;

    __shared__ ulonglong2 xs[4][BP][NPC];   // 16KB
    __shared__ float es[NPC * CC];          // 4KB

    const float4* x4 = (const float4*)x;
    XS_LOAD(xs, x4, bg, n0, t);
    if (use_e) {
        for (int idx = t; idx < NPC * CC; idx += 256)
            es[idx] = g_e[(size_t)n0 * CC + idx];
    }
    __syncthreads();

    u64 acc0[BP], acc1[BP];
#pragma unroll
    for (int bp = 0; bp < BP; bp++) { acc0[bp] = 0ull; acc1[bp] = 0ull; }

    const float4* wp = (const float4*)(W + (size_t)n0 * WROW + (size_t)(2 * t) * II);
    float4 wa0 = wp[0], wa1 = wp[1], wb0 = wp[2], wb1 = wp[3];

    for (int nn = 0; nn < NPC; nn++) {
        float cw = use_e ? es[nn * CC + c] : (1.0f / (float)NN);
        u64 wc0[8], wc1[8];
        {
            float m;
            m = wa0.x * cw; wc0[0] = pk2(m, m);
            m = wa0.y * cw; wc0[1] = pk2(m, m);
            m = wa0.z * cw; wc0[2] = pk2(m, m);
            m = wa0.w * cw; wc0[3] = pk2(m, m);
            m = wa1.x * cw; wc0[4] = pk2(m, m);
            m = wa1.y * cw; wc0[5] = pk2(m, m);
            m = wa1.z * cw; wc0[6] = pk2(m, m);
            m = wa1.w * cw; wc0[7] = pk2(m, m);
            m = wb0.x * cw; wc1[0] = pk2(m, m);
            m = wb0.y * cw; wc1[1] = pk2(m, m);
            m = wb0.z * cw; wc1[2] = pk2(m, m);
            m = wb0.w * cw; wc1[3] = pk2(m, m);
            m = wb1.x * cw; wc1[4] = pk2(m, m);
            m = wb1.y * cw; wc1[5] = pk2(m, m);
            m = wb1.z * cw; wc1[6] = pk2(m, m);
            m = wb1.w * cw; wc1[7] = pk2(m, m);
        }
        if (nn + 1 < NPC) {
            const float4* wn = wp + (size_t)(nn + 1) * (WROW / 4);
            wa0 = wn[0]; wa1 = wn[1]; wb0 = wn[2]; wb1 = wn[3];
        }
#pragma unroll
        for (int bp = 0; bp < BP; bp++) {
            ulonglong2 x01 = xs[0][bp][nn];
            ulonglong2 x23 = xs[1][bp][nn];
            ulonglong2 x45 = xs[2][bp][nn];
            ulonglong2 x67 = xs[3][bp][nn];
            u64 a0 = acc0[bp], a1 = acc1[bp];
            a0 = ffma2(wc0[0], x01.x, a0); a1 = ffma2(wc1[0], x01.x, a1);
            a0 = ffma2(wc0[1], x01.y, a0); a1 = ffma2(wc1[1], x01.y, a1);
            a0 = ffma2(wc0[2], x23.x, a0); a1 = ffma2(wc1[2], x23.x, a1);
            a0 = ffma2(wc0[3], x23.y, a0); a1 = ffma2(wc1[3], x23.y, a1);
            a0 = ffma2(wc0[4], x45.x, a0); a1 = ffma2(wc1[4], x45.x, a1);
            a0 = ffma2(wc0[5], x45.y, a0); a1 = ffma2(wc1[5], x45.y, a1);
            a0 = ffma2(wc0[6], x67.x, a0); a1 = ffma2(wc1[6], x67.x, a1);
            a0 = ffma2(wc0[7], x67.y, a0); a1 = ffma2(wc1[7], x67.y, a1);
            acc0[bp] = a0; acc1[bp] = a1;
        }
    }

    float* sp = g_spart + ((size_t)chunk * BB + (size_t)bg * BG) * CO + 2 * t;
#pragma unroll
    for (int bp = 0; bp < BP; bp++) {
        float2 f0 = unpk(acc0[bp]);   // (s[b0,co0], s[b1,co0])
        float2 f1 = unpk(acc1[bp]);   // (s[b0,co1], s[b1,co1])
        *(float2*)(sp + (size_t)(2 * bp) * CO)     = make_float2(f0.x, f1.x);
        *(float2*)(sp + (size_t)(2 * bp + 1) * CO) = make_float2(f0.y, f1.y);
    }
}

// ---------------------------------------------------------------------------
// k_bupd: agreement partials; recompute t per n, dot with v (b-pair packed).
// Writes g_bupd in [bg][c][n] layout (coalesced consumption by k_route2).
// ---------------------------------------------------------------------------
__global__ __launch_bounds__(256, 2)
void k_bupd(const float* __restrict__ x, const float* __restrict__ W)
{
    const int chunk = blockIdx.x;
    const int bg    = blockIdx.y;
    const int t     = threadIdx.x;
    const int n0    = chunk * NPC;

    __shared__ ulonglong2 xs[4][BP][NPC];   // 16KB

    const float4* x4 = (const float4*)x;
    XS_LOAD(xs, x4, bg, n0, t);
    __syncthreads();

    u64 vp0[BP], vp1[BP];
#pragma unroll
    for (int bp = 0; bp < BP; bp++) {
        const float* v0 = g_v + (size_t)(bg * BG + 2 * bp) * CO + 2 * t;
        const float* v1 = g_v + (size_t)(bg * BG + 2 * bp + 1) * CO + 2 * t;
        float2 a = *(const float2*)v0;   // (v[b0,co0], v[b0,co1])
        float2 b = *(const float2*)v1;
        vp0[bp] = pk2(a.x, b.x);         // (v[b0,co0], v[b1,co0])
        vp1[bp] = pk2(a.y, b.y);         // (v[b0,co1], v[b1,co1])
    }

    const float4* wp = (const float4*)(W + (size_t)n0 * WROW + (size_t)(2 * t) * II);
    float4 wa0 = wp[0], wa1 = wp[1], wb0 = wp[2], wb1 = wp[3];

    for (int nn = 0; nn < NPC; nn++) {
        u64 wd0[8], wd1[8];
        wd0[0] = pk2(wa0.x, wa0.x); wd0[1] = pk2(wa0.y, wa0.y);
        wd0[2] = pk2(wa0.z, wa0.z); wd0[3] = pk2(wa0.w, wa0.w);
        wd0[4] = pk2(wa1.x, wa1.x); wd0[5] = pk2(wa1.y, wa1.y);
        wd0[6] = pk2(wa1.z, wa1.z); wd0[7] = pk2(wa1.w, wa1.w);
        wd1[0] = pk2(wb0.x, wb0.x); wd1[1] = pk2(wb0.y, wb0.y);
        wd1[2] = pk2(wb0.z, wb0.z); wd1[3] = pk2(wb0.w, wb0.w);
        wd1[4] = pk2(wb1.x, wb1.x); wd1[5] = pk2(wb1.y, wb1.y);
        wd1[6] = pk2(wb1.z, wb1.z); wd1[7] = pk2(wb1.w, wb1.w);
        if (nn + 1 < NPC) {
            const float4* wn = wp + (size_t)(nn + 1) * (WROW / 4);
            wa0 = wn[0]; wa1 = wn[1]; wb0 = wn[2]; wb1 = wn[3];
        }
        u64 pacc = 0ull;
#pragma unroll
        for (int bp = 0; bp < BP; bp++) {
            ulonglong2 x01 = xs[0][bp][nn];
            ulonglong2 x23 = xs[1][bp][nn];
            ulonglong2 x45 = xs[2][bp][nn];
            ulonglong2 x67 = xs[3][bp][nn];
            u64 t0 = fmul2(wd0[0], x01.x);
            u64 t1 = fmul2(wd1[0], x01.x);
            t0 = ffma2(wd0[1], x01.y, t0); t1 = ffma2(wd1[1], x01.y, t1);
            t0 = ffma2(wd0[2], x23.x, t0); t1 = ffma2(wd1[2], x23.x, t1);
            t0 = ffma2(wd0[3], x23.y, t0); t1 = ffma2(wd1[3], x23.y, t1);
            t0 = ffma2(wd0[4], x45.x, t0); t1 = ffma2(wd1[4], x45.x, t1);
            t0 = ffma2(wd0[5], x45.y, t0); t1 = ffma2(wd1[5], x45.y, t1);
            t0 = ffma2(wd0[6], x67.x, t0); t1 = ffma2(wd1[6], x67.x, t1);
            t0 = ffma2(wd0[7], x67.y, t0); t1 = ffma2(wd1[7], x67.y, t1);
            pacc = ffma2(t0, vp0[bp], pacc);
            pacc = ffma2(t1, vp1[bp], pacc);
        }
        float2 pv = unpk(pacc);
        float p = pv.x + pv.y;
        p += __shfl_down_sync(0xffffffffu, p, 4, 8);
        p += __shfl_down_sync(0xffffffffu, p, 2, 8);
        p += __shfl_down_sync(0xffffffffu, p, 1, 8);
        if ((t & 7) == 0)
            g_bupd[(size_t)bg * (CC * NN) + (size_t)(t >> 3) * NN + (n0 + nn)] = p;
    }
}

// ---------------------------------------------------------------------------
// k_squash: float2 partial reduce + squash. 16384 float2 ids, 128 blocks.
// ---------------------------------------------------------------------------
__global__ void k_squash(float* __restrict__ dout, int uniform, int final_pass)
{
    int id2 = blockIdx.x * 128 + threadIdx.x;   // 0..16383 (b*256 + co/2)
    const float2* sp = (const float2*)g_spart;
    float sx = 0.0f, sy = 0.0f;
#pragma unroll 8
    for (int ch = 0; ch < NCHUNK; ch++) {
        float2 p = sp[(size_t)ch * 16384 + id2];
        sx += p.x; sy += p.y;
    }
    int c = (id2 >> 3) & 31;
    float scale = uniform ? 1.0f : g_inv[c];
    sx *= scale; sy *= scale;
    float2 v;
    v.x = sx * fabsf(sx) / (1.0f + sx * sx);
    v.y = sy * fabsf(sy) / (1.0f + sy * sy);
    if (final_pass) ((float2*)dout)[id2] = v;
    else            ((float2*)g_v)[id2]  = v;
}

// ---------------------------------------------------------------------------
// k_route2: ONE kernel replacing bcomb+esum. One block per c; g_bupd/[bg][c][n]
// and g_b/[c][n] rows are contiguous -> fully coalesced reads (fixes R6's
// strided k_route). g_e written scattered [n][c] (stores are fire-and-forget).
// ---------------------------------------------------------------------------
__global__ void k_route2(int iter0)
{
    const int c = blockIdx.x;
    const int t = threadIdx.x;
    __shared__ float red[256];

    const float* bu0 = g_bupd + (size_t)0 * (CC * NN) + (size_t)c * NN;
    const float* bu1 = g_bupd + (size_t)1 * (CC * NN) + (size_t)c * NN;
    const float* bu2 = g_bupd + (size_t)2 * (CC * NN) + (size_t)c * NN;
    const float* bu3 = g_bupd + (size_t)3 * (CC * NN) + (size_t)c * NN;
    float* brow = g_b + (size_t)c * NN;

    float local = 0.0f;
    for (int n = t; n < NN; n += 256) {
        float a = (bu0[n] + bu1[n] + bu2[n] + bu3[n]) * (1.0f / (float)BB);
        float bb = iter0 ? a : (brow[n] + a);
        brow[n] = bb;
        float e = expf(bb);
        g_e[(size_t)n * CC + c] = e;
        local += e;
    }
    red[t] = local;
    __syncthreads();
    for (int off = 128; off > 0; off >>= 1) {
        if (t < off) red[t] += red[t + off];
        __syncthreads();
    }
    if (t == 0) g_inv[c] = 1.0f / red[0];
}

// ---------------------------------------------------------------------------
extern "C" void kernel_launch(void* const* d_in, const int* in_sizes, int n_in,
                              void* d_out, int out_size)
{
    const float* x = (const float*)d_in[0];   // [B, N, I]
    const float* W = (const float*)d_in[1];   // [N, C, O, I]
    float* out = (float*)d_out;               // [B, C, O, 1]

    dim3 g(NCHUNK, NBG);

    // iteration 0 (uniform weights 1/N inside k_sj)
    k_sj<<<g, 256>>>(x, W, 0);
    k_squash<<<128, 128>>>(out, 1, 0);
    k_bupd<<<g, 256>>>(x, W);
    k_route2<<<CC, 256>>>(1);

    // iteration 1 (weights = exp(b), normalized in squash)
    k_sj<<<g, 256>>>(x, W, 1);
    k_squash<<<128, 128>>>(out, 0, 0);
    k_bupd<<<g, 256>>>(x, W);
    k_route2<<<CC, 256>>>(0);

    // iteration 2 (final)
    k_sj<<<g, 256>>>(x, W, 1);
    k_squash<<<128, 128>>>(out, 0, 1);
}

// round 16
// speedup vs baseline: 1.0639x; 1.0053x over previous
#include <cuda_runtime.h>
#include <math.h>

// CapsuleLayer dynamic routing v13: v6 (best, 219.2us) with k_esum eliminated
// via threadfence-reduction inside k_bcomb (last-arriving block computes the
// per-c exp-sum reciprocals; int-counter atomic only -> deterministic).

#define BB 64
#define NN 2304
#define CC 32
#define OO 16
#define II 8
#define CO 512
#define WROW 4096     // C*O*I floats per n
#define NCHUNK 72
#define NPC 32        // NN / NCHUNK
#define BG 16         // batch rows per block
#define BP 8          // b-pairs per block
#define NBG 4

__device__ float g_spart[(size_t)NCHUNK * BB * CO];  // 9.4 MB
__device__ float g_v[BB * CO];
__device__ float g_bupd[NBG * NN * CC];
__device__ float g_b[NN * CC];
__device__ float g_e[NN * CC];
__device__ float g_epart[288 * CC];
__device__ float g_inv[CC];
__device__ int   g_ctr = 0;

typedef unsigned long long u64;

__device__ __forceinline__ u64 pk2(float lo, float hi) {
    u64 r; asm("mov.b64 %0,{%1,%2};" : "=l"(r) : "f"(lo), "f"(hi)); return r;
}
__device__ __forceinline__ float2 unpk(u64 v) {
    float2 r; asm("mov.b64 {%0,%1},%2;" : "=f"(r.x), "=f"(r.y) : "l"(v)); return r;
}
__device__ __forceinline__ u64 ffma2(u64 a, u64 b, u64 c) {
    u64 d; asm("fma.rn.f32x2 %0,%1,%2,%3;" : "=l"(d) : "l"(a), "l"(b), "l"(c)); return d;
}
__device__ __forceinline__ u64 fmul2(u64 a, u64 b) {
    u64 d; asm("mul.rn.f32x2 %0,%1,%2;" : "=l"(d) : "l"(a), "l"(b)); return d;
}

// shared x tile: xs[ipair(4)][bp(8)][nn(32)] of ulonglong2 = 16KB
#define XS_LOAD(xs, x4, bg, n0, t)                                              \
    {                                                                            \
        int bp = (t) >> 5;                                                       \
        int nn = (t) & 31;                                                       \
        const float4* xp0 = (x4) + ((size_t)((bg) * BG + 2 * bp) * NN + ((n0) + nn)) * 2; \
        const float4* xp1 = (x4) + ((size_t)((bg) * BG + 2 * bp + 1) * NN + ((n0) + nn)) * 2; \
        float4 a0 = xp0[0], a1 = xp0[1];                                         \
        float4 c0 = xp1[0], c1 = xp1[1];                                         \
        xs[0][bp][nn] = make_ulonglong2(pk2(a0.x, c0.x), pk2(a0.y, c0.y));       \
        xs[1][bp][nn] = make_ulonglong2(pk2(a0.z, c0.z), pk2(a0.w, c0.w));       \
        xs[2][bp][nn] = make_ulonglong2(pk2(a1.x, c1.x), pk2(a1.y, c1.y));       \
        xs[3][bp][nn] = make_ulonglong2(pk2(a1.z, c1.z), pk2(a1.w, c1.w));       \
    }

// ---------------------------------------------------------------------------
// k_sj: s partials. block = (n-chunk of 32, b-group of 16); 256 threads.
// ---------------------------------------------------------------------------
__global__ __launch_bounds__(256, 2)
void k_sj(const float* __restrict__ x, const float* __restrict__ W, int use_e)
{
    const int chunk = blockIdx.x;
    const int bg    = blockIdx.y;
    const int t     = threadIdx.x;
    const int n0    = chunk * NPC;
    const int c     = t >> 3;

    __shared__ ulonglong2 xs[4][BP][NPC];   // 16KB
    __shared__ float es[NPC * CC];          // 4KB

    const float4* x4 = (const float4*)x;
    XS_LOAD(xs, x4, bg, n0, t);
    if (use_e) {
        for (int idx = t; idx < NPC * CC; idx += 256)
            es[idx] = g_e[(size_t)n0 * CC + idx];
    }
    __syncthreads();

    u64 acc0[BP], acc1[BP];
#pragma unroll
    for (int bp = 0; bp < BP; bp++) { acc0[bp] = 0ull; acc1[bp] = 0ull; }

    const float4* wp = (const float4*)(W + (size_t)n0 * WROW + (size_t)(2 * t) * II);
    float4 wa0 = wp[0], wa1 = wp[1], wb0 = wp[2], wb1 = wp[3];

    for (int nn = 0; nn < NPC; nn++) {
        float cw = use_e ? es[nn * CC + c] : (1.0f / (float)NN);
        u64 wc0[8], wc1[8];
        {
            float m;
            m = wa0.x * cw; wc0[0] = pk2(m, m);
            m = wa0.y * cw; wc0[1] = pk2(m, m);
            m = wa0.z * cw; wc0[2] = pk2(m, m);
            m = wa0.w * cw; wc0[3] = pk2(m, m);
            m = wa1.x * cw; wc0[4] = pk2(m, m);
            m = wa1.y * cw; wc0[5] = pk2(m, m);
            m = wa1.z * cw; wc0[6] = pk2(m, m);
            m = wa1.w * cw; wc0[7] = pk2(m, m);
            m = wb0.x * cw; wc1[0] = pk2(m, m);
            m = wb0.y * cw; wc1[1] = pk2(m, m);
            m = wb0.z * cw; wc1[2] = pk2(m, m);
            m = wb0.w * cw; wc1[3] = pk2(m, m);
            m = wb1.x * cw; wc1[4] = pk2(m, m);
            m = wb1.y * cw; wc1[5] = pk2(m, m);
            m = wb1.z * cw; wc1[6] = pk2(m, m);
            m = wb1.w * cw; wc1[7] = pk2(m, m);
        }
        if (nn + 1 < NPC) {
            const float4* wn = wp + (size_t)(nn + 1) * (WROW / 4);
            wa0 = wn[0]; wa1 = wn[1]; wb0 = wn[2]; wb1 = wn[3];
        }
#pragma unroll
        for (int bp = 0; bp < BP; bp++) {
            ulonglong2 x01 = xs[0][bp][nn];
            ulonglong2 x23 = xs[1][bp][nn];
            ulonglong2 x45 = xs[2][bp][nn];
            ulonglong2 x67 = xs[3][bp][nn];
            u64 a0 = acc0[bp], a1 = acc1[bp];
            a0 = ffma2(wc0[0], x01.x, a0); a1 = ffma2(wc1[0], x01.x, a1);
            a0 = ffma2(wc0[1], x01.y, a0); a1 = ffma2(wc1[1], x01.y, a1);
            a0 = ffma2(wc0[2], x23.x, a0); a1 = ffma2(wc1[2], x23.x, a1);
            a0 = ffma2(wc0[3], x23.y, a0); a1 = ffma2(wc1[3], x23.y, a1);
            a0 = ffma2(wc0[4], x45.x, a0); a1 = ffma2(wc1[4], x45.x, a1);
            a0 = ffma2(wc0[5], x45.y, a0); a1 = ffma2(wc1[5], x45.y, a1);
            a0 = ffma2(wc0[6], x67.x, a0); a1 = ffma2(wc1[6], x67.x, a1);
            a0 = ffma2(wc0[7], x67.y, a0); a1 = ffma2(wc1[7], x67.y, a1);
            acc0[bp] = a0; acc1[bp] = a1;
        }
    }

    float* sp = g_spart + ((size_t)chunk * BB + (size_t)bg * BG) * CO + 2 * t;
#pragma unroll
    for (int bp = 0; bp < BP; bp++) {
        float2 f0 = unpk(acc0[bp]);   // (s[b0,co0], s[b1,co0])
        float2 f1 = unpk(acc1[bp]);   // (s[b0,co1], s[b1,co1])
        *(float2*)(sp + (size_t)(2 * bp) * CO)     = make_float2(f0.x, f1.x);
        *(float2*)(sp + (size_t)(2 * bp + 1) * CO) = make_float2(f0.y, f1.y);
    }
}

// ---------------------------------------------------------------------------
// k_bupd: agreement partials; recompute t per n, dot with v (b-pair packed).
// ---------------------------------------------------------------------------
__global__ __launch_bounds__(256, 2)
void k_bupd(const float* __restrict__ x, const float* __restrict__ W)
{
    const int chunk = blockIdx.x;
    const int bg    = blockIdx.y;
    const int t     = threadIdx.x;
    const int n0    = chunk * NPC;

    __shared__ ulonglong2 xs[4][BP][NPC];   // 16KB

    const float4* x4 = (const float4*)x;
    XS_LOAD(xs, x4, bg, n0, t);
    __syncthreads();

    u64 vp0[BP], vp1[BP];
#pragma unroll
    for (int bp = 0; bp < BP; bp++) {
        const float* v0 = g_v + (size_t)(bg * BG + 2 * bp) * CO + 2 * t;
        const float* v1 = g_v + (size_t)(bg * BG + 2 * bp + 1) * CO + 2 * t;
        float2 a = *(const float2*)v0;   // (v[b0,co0], v[b0,co1])
        float2 b = *(const float2*)v1;
        vp0[bp] = pk2(a.x, b.x);         // (v[b0,co0], v[b1,co0])
        vp1[bp] = pk2(a.y, b.y);         // (v[b0,co1], v[b1,co1])
    }

    const float4* wp = (const float4*)(W + (size_t)n0 * WROW + (size_t)(2 * t) * II);
    float4 wa0 = wp[0], wa1 = wp[1], wb0 = wp[2], wb1 = wp[3];

    for (int nn = 0; nn < NPC; nn++) {
        u64 wd0[8], wd1[8];
        wd0[0] = pk2(wa0.x, wa0.x); wd0[1] = pk2(wa0.y, wa0.y);
        wd0[2] = pk2(wa0.z, wa0.z); wd0[3] = pk2(wa0.w, wa0.w);
        wd0[4] = pk2(wa1.x, wa1.x); wd0[5] = pk2(wa1.y, wa1.y);
        wd0[6] = pk2(wa1.z, wa1.z); wd0[7] = pk2(wa1.w, wa1.w);
        wd1[0] = pk2(wb0.x, wb0.x); wd1[1] = pk2(wb0.y, wb0.y);
        wd1[2] = pk2(wb0.z, wb0.z); wd1[3] = pk2(wb0.w, wb0.w);
        wd1[4] = pk2(wb1.x, wb1.x); wd1[5] = pk2(wb1.y, wb1.y);
        wd1[6] = pk2(wb1.z, wb1.z); wd1[7] = pk2(wb1.w, wb1.w);
        if (nn + 1 < NPC) {
            const float4* wn = wp + (size_t)(nn + 1) * (WROW / 4);
            wa0 = wn[0]; wa1 = wn[1]; wb0 = wn[2]; wb1 = wn[3];
        }
        u64 pacc = 0ull;
#pragma unroll
        for (int bp = 0; bp < BP; bp++) {
            ulonglong2 x01 = xs[0][bp][nn];
            ulonglong2 x23 = xs[1][bp][nn];
            ulonglong2 x45 = xs[2][bp][nn];
            ulonglong2 x67 = xs[3][bp][nn];
            u64 t0 = fmul2(wd0[0], x01.x);
            u64 t1 = fmul2(wd1[0], x01.x);
            t0 = ffma2(wd0[1], x01.y, t0); t1 = ffma2(wd1[1], x01.y, t1);
            t0 = ffma2(wd0[2], x23.x, t0); t1 = ffma2(wd1[2], x23.x, t1);
            t0 = ffma2(wd0[3], x23.y, t0); t1 = ffma2(wd1[3], x23.y, t1);
            t0 = ffma2(wd0[4], x45.x, t0); t1 = ffma2(wd1[4], x45.x, t1);
            t0 = ffma2(wd0[5], x45.y, t0); t1 = ffma2(wd1[5], x45.y, t1);
            t0 = ffma2(wd0[6], x67.x, t0); t1 = ffma2(wd1[6], x67.x, t1);
            t0 = ffma2(wd0[7], x67.y, t0); t1 = ffma2(wd1[7], x67.y, t1);
            pacc = ffma2(t0, vp0[bp], pacc);
            pacc = ffma2(t1, vp1[bp], pacc);
        }
        float2 pv = unpk(pacc);
        float p = pv.x + pv.y;
        p += __shfl_down_sync(0xffffffffu, p, 4, 8);
        p += __shfl_down_sync(0xffffffffu, p, 2, 8);
        p += __shfl_down_sync(0xffffffffu, p, 1, 8);
        if ((t & 7) == 0)
            g_bupd[(size_t)bg * (NN * CC) + (size_t)(n0 + nn) * CC + (t >> 3)] = p;
    }
}

// ---------------------------------------------------------------------------
// k_squash: float2 partial reduce + squash. 16384 float2 ids, 128 blocks.
// ---------------------------------------------------------------------------
__global__ void k_squash(float* __restrict__ dout, int uniform, int final_pass)
{
    int id2 = blockIdx.x * 128 + threadIdx.x;   // 0..16383 (b*256 + co/2)
    const float2* sp = (const float2*)g_spart;
    float sx = 0.0f, sy = 0.0f;
#pragma unroll 8
    for (int ch = 0; ch < NCHUNK; ch++) {
        float2 p = sp[(size_t)ch * 16384 + id2];
        sx += p.x; sy += p.y;
    }
    int c = (id2 >> 3) & 31;
    float scale = uniform ? 1.0f : g_inv[c];
    sx *= scale; sy *= scale;
    float2 v;
    v.x = sx * fabsf(sx) / (1.0f + sx * sx);
    v.y = sy * fabsf(sy) / (1.0f + sy * sy);
    if (final_pass) ((float2*)dout)[id2] = v;
    else            ((float2*)g_v)[id2]  = v;
}

// ---------------------------------------------------------------------------
// k_bcomb: combine 4 agreement partials, update b, e = exp(b), per-block
// partial e-sums; the LAST-arriving block (int-atomic counter) sums the 288
// partials per c and writes g_inv. Deterministic: partial contents and the
// last block's summation order are fixed; only arrival order is atomic.
// ---------------------------------------------------------------------------
__global__ void k_bcomb(int iter0)
{
    const int t   = threadIdx.x;
    const int idx = blockIdx.x * 256 + t;     // n*32 + c

    float a = g_bupd[idx]
            + g_bupd[(size_t)NN * CC + idx]
            + g_bupd[(size_t)2 * NN * CC + idx]
            + g_bupd[(size_t)3 * NN * CC + idx];
    a *= (1.0f / (float)BB);

    float bb = iter0 ? a : (g_b[idx] + a);
    g_b[idx] = bb;
    float e = expf(bb);
    g_e[idx] = e;

    __shared__ float sred[256];
    __shared__ int   is_last;
    sred[t] = e;
    __syncthreads();
    if (t < 32) {
        float s = 0.0f;
#pragma unroll
        for (int r = 0; r < 8; r++) s += sred[r * 32 + t];
        g_epart[blockIdx.x * 32 + t] = s;
    }

    // last-block reduction of g_epart -> g_inv
    __threadfence();
    __syncthreads();
    if (t == 0) {
        int old = atomicAdd(&g_ctr, 1);
        is_last = (old == 287) ? 1 : 0;
    }
    __syncthreads();
    if (is_last) {
        const int c = t & 31;
        const int grp = t >> 5;               // 0..7
        float s = 0.0f;
        for (int i = grp; i < 288; i += 8)    // fixed order per (grp)
            s += g_epart[i * 32 + c];
        sred[t] = s;
        __syncthreads();
        if (t < 32) {
            float tot = 0.0f;
#pragma unroll
            for (int r = 0; r < 8; r++) tot += sred[r * 32 + t];
            g_inv[t] = 1.0f / tot;
        }
        if (t == 0) g_ctr = 0;                // reset for next launch / replay
    }
}

// ---------------------------------------------------------------------------
extern "C" void kernel_launch(void* const* d_in, const int* in_sizes, int n_in,
                              void* d_out, int out_size)
{
    const float* x = (const float*)d_in[0];   // [B, N, I]
    const float* W = (const float*)d_in[1];   // [N, C, O, I]
    float* out = (float*)d_out;               // [B, C, O, 1]

    dim3 g(NCHUNK, NBG);

    // iteration 0 (uniform weights 1/N inside k_sj)
    k_sj<<<g, 256>>>(x, W, 0);
    k_squash<<<128, 128>>>(out, 1, 0);
    k_bupd<<<g, 256>>>(x, W);
    k_bcomb<<<288, 256>>>(1);

    // iteration 1 (weights = exp(b), normalized in squash)
    k_sj<<<g, 256>>>(x, W, 1);
    k_squash<<<128, 128>>>(out, 0, 0);
    k_bupd<<<g, 256>>>(x, W);
    k_bcomb<<<288, 256>>>(0);

    // iteration 2 (final)
    k_sj<<<g, 256>>>(x, W, 1);
    k_squash<<<128, 128>>>(out, 0, 1);
}